// round 2
// baseline (speedup 1.0000x reference)
#include <cuda_runtime.h>
#include <cuda_bf16.h>

#define N_NODES_MAX 100000
#define D 128

// Scratch (allocation-free requirement -> __device__ globals), 16B-aligned for float4
__device__ __align__(16) float g_deg[N_NODES_MAX];             // degree (incl. self loop)
__device__ __align__(16) float g_isd[N_NODES_MAX];             // deg^-1/2
__device__ __align__(16) float g_h[(size_t)N_NODES_MAX * D];   // transformed features
__device__ __align__(16) float g_agg[(size_t)N_NODES_MAX * D]; // scatter accumulator
__device__ int g_is64;                                          // edge_index dtype flag

// ---------------------------------------------------------------------------
// Edge-index dtype detection. Node ids < 2^31, so for little-endian int64 the
// odd 32-bit words are all zero; for int32 they are random node ids.
// Reads only the first 2048 words (within bounds for either layout).
// ---------------------------------------------------------------------------
__global__ void detect_dtype_kernel(const unsigned int* __restrict__ w) {
    __shared__ int any_nz;
    if (threadIdx.x == 0) any_nz = 0;
    __syncthreads();
    for (int i = threadIdx.x; i < 1024; i += blockDim.x)
        if (w[2 * i + 1] != 0u) any_nz = 1;
    __syncthreads();
    if (threadIdx.x == 0) g_is64 = any_nz ? 0 : 1;
}

// Read edge endpoint at logical position pos (src: pos in [0,E), dst: [E,2E))
__device__ __forceinline__ int edge_at(const unsigned int* __restrict__ w,
                                       size_t pos, int is64) {
    return (int)(is64 ? w[2 * pos] : w[pos]);
}

// ---------------------------------------------------------------------------
// degree kernels
// ---------------------------------------------------------------------------
__global__ void init_deg_kernel(float* deg, int n) {
    int i = blockIdx.x * blockDim.x + threadIdx.x;
    if (i < n) deg[i] = 1.0f;  // self loop
}

__global__ void count_deg_kernel(const unsigned int* __restrict__ ei, float* deg, int E) {
    int e = blockIdx.x * blockDim.x + threadIdx.x;
    if (e < E) {
        int d = edge_at(ei, (size_t)E + e, g_is64);
        atomicAdd(deg + d, 1.0f);
    }
}

__global__ void isd_kernel(const float* __restrict__ deg, float* isd, int n) {
    int i = blockIdx.x * blockDim.x + threadIdx.x;
    if (i < n) isd[i] = rsqrtf(deg[i]);
}

// ---------------------------------------------------------------------------
// GEMM: [M,128] @ [128,128], optional fused relu(x + bias_in) on the input,
// epilogue writes h and agg = h * (isd^2) (self-loop contribution).
// Tile: 64 rows x 128 cols per CTA of 256 threads. W + A tile staged in smem.
// In-place safe (A == AggOut): full A tile is staged before any write.
// ---------------------------------------------------------------------------
template <bool IN_TRANS>
__global__ void gemm128_kernel(const float* __restrict__ A,
                               const float* __restrict__ bias_in,
                               const float* __restrict__ W,
                               float* __restrict__ Hout,
                               float* __restrict__ AggOut,
                               const float* __restrict__ isd,
                               int M) {
    extern __shared__ float sm[];
    float* Ws = sm;             // 128*128
    float* As = sm + 128 * 128; // 64*128

    const int tid = threadIdx.x;
    const int r0 = blockIdx.x * 64;

    // Load W (128x128 fp32 = 64KB)
    const float4* W4 = (const float4*)W;
    float4* Ws4 = (float4*)Ws;
#pragma unroll
    for (int i = 0; i < 16; i++) Ws4[tid + i * 256] = W4[tid + i * 256];

    // Load A tile (64x128), optionally relu(v + bias_in)
    float4* As4 = (float4*)As;
#pragma unroll
    for (int i = 0; i < 8; i++) {
        int idx = tid + i * 256;      // float4 index in tile
        int row = r0 + (idx >> 5);
        float4 v = make_float4(0.f, 0.f, 0.f, 0.f);
        if (row < M) {
            v = ((const float4*)A)[(size_t)row * 32 + (idx & 31)];
            if (IN_TRANS) {
                float4 b = ((const float4*)bias_in)[idx & 31];
                v.x = fmaxf(v.x + b.x, 0.f);
                v.y = fmaxf(v.y + b.y, 0.f);
                v.z = fmaxf(v.z + b.z, 0.f);
                v.w = fmaxf(v.w + b.w, 0.f);
            }
        }
        As4[idx] = v;
    }
    __syncthreads();

    const int tx = tid & 31;   // col group: cols tx*4 .. tx*4+3
    const int ty = tid >> 5;   // row group: rows ty*8 .. ty*8+7
    float acc[8][4] = {};

#pragma unroll 4
    for (int k = 0; k < 128; k++) {
        float4 w = ((const float4*)Ws)[k * 32 + tx];
#pragma unroll
        for (int i = 0; i < 8; i++) {
            float a = As[(ty * 8 + i) * 128 + k];
            acc[i][0] += a * w.x;
            acc[i][1] += a * w.y;
            acc[i][2] += a * w.z;
            acc[i][3] += a * w.w;
        }
    }

#pragma unroll
    for (int i = 0; i < 8; i++) {
        int row = r0 + ty * 8 + i;
        if (row < M) {
            float4 v = make_float4(acc[i][0], acc[i][1], acc[i][2], acc[i][3]);
            ((float4*)Hout)[(size_t)row * 32 + tx] = v;
            float s = isd[row];
            float inv = s * s;  // self-loop norm = 1/deg
            float4 u = make_float4(v.x * inv, v.y * inv, v.z * inv, v.w * inv);
            ((float4*)AggOut)[(size_t)row * 32 + tx] = u;
        }
    }
}

// ---------------------------------------------------------------------------
// Edge aggregation: one warp per edge; each lane handles a float4 (32*4 = 128).
// agg[dst] += h[src] * isd[src]*isd[dst], via sm_90+ vector atomics.
// ---------------------------------------------------------------------------
__global__ void agg_kernel(const unsigned int* __restrict__ ei,
                           const float* __restrict__ h,
                           const float* __restrict__ isd,
                           float* __restrict__ agg,
                           int E) {
    int warp = (blockIdx.x * blockDim.x + threadIdx.x) >> 5;
    int lane = threadIdx.x & 31;
    if (warp >= E) return;
    int is64 = g_is64;
    int s = edge_at(ei, (size_t)warp, is64);
    int d = edge_at(ei, (size_t)E + warp, is64);
    float norm = isd[s] * isd[d];
    float4 v = ((const float4*)h)[(size_t)s * 32 + lane];
    v.x *= norm; v.y *= norm; v.z *= norm; v.w *= norm;
    atomicAdd(((float4*)agg) + (size_t)d * 32 + lane, v);
}

// ---------------------------------------------------------------------------
// Head GEMM: out[M,40] = relu(A + b2) @ Wl + bl
// Tile: 128 rows x 40 cols per CTA of 128 threads; A staged padded (129) in smem.
// ---------------------------------------------------------------------------
__global__ void head_kernel(const float* __restrict__ A,
                            const float* __restrict__ b2,
                            const float* __restrict__ Wl,
                            const float* __restrict__ bl,
                            float* __restrict__ out,
                            int M) {
    extern __shared__ float sm[];
    float* Ws = sm;             // 128*40
    float* As = sm + 128 * 40;  // 128*129 (padded)

    const int tid = threadIdx.x; // 128 threads
    const int r0 = blockIdx.x * 128;

    for (int i = tid; i < 128 * 40; i += 128) Ws[i] = Wl[i];

#pragma unroll
    for (int i = 0; i < 32; i++) {
        int idx = tid + i * 128;       // float4 index
        int lr = idx >> 5;             // local row
        int c4 = idx & 31;
        int row = r0 + lr;
        float4 v = make_float4(0.f, 0.f, 0.f, 0.f);
        if (row < M) {
            v = ((const float4*)A)[(size_t)row * 32 + c4];
            float4 b = ((const float4*)b2)[c4];
            v.x = fmaxf(v.x + b.x, 0.f);
            v.y = fmaxf(v.y + b.y, 0.f);
            v.z = fmaxf(v.z + b.z, 0.f);
            v.w = fmaxf(v.w + b.w, 0.f);
        }
        float* dst = As + lr * 129 + c4 * 4;
        dst[0] = v.x; dst[1] = v.y; dst[2] = v.z; dst[3] = v.w;
    }
    __syncthreads();

    const int rg = tid >> 2;  // 0..31 -> rows rg*4..rg*4+3
    const int cg = tid & 3;   // cols cg*10..cg*10+9
    float acc[4][10] = {};

    for (int k = 0; k < 128; k++) {
        float w[10];
#pragma unroll
        for (int j = 0; j < 10; j++) w[j] = Ws[k * 40 + cg * 10 + j];
#pragma unroll
        for (int i = 0; i < 4; i++) {
            float a = As[(rg * 4 + i) * 129 + k];
#pragma unroll
            for (int j = 0; j < 10; j++) acc[i][j] += a * w[j];
        }
    }

#pragma unroll
    for (int i = 0; i < 4; i++) {
        int row = r0 + rg * 4 + i;
        if (row < M) {
#pragma unroll
            for (int j = 0; j < 10; j++)
                out[(size_t)row * 40 + cg * 10 + j] = acc[i][j] + bl[cg * 10 + j];
        }
    }
}

// ---------------------------------------------------------------------------
extern "C" void kernel_launch(void* const* d_in, const int* in_sizes, int n_in,
                              void* d_out, int out_size) {
    const float* x = (const float*)d_in[0];
    const unsigned int* ei = (const unsigned int*)d_in[1];
    const float* W1 = (const float*)d_in[2];
    const float* b1 = (const float*)d_in[3];
    const float* W2 = (const float*)d_in[4];
    const float* b2 = (const float*)d_in[5];
    const float* Wl = (const float*)d_in[6];
    const float* bl = (const float*)d_in[7];
    float* out = (float*)d_out;

    const int N = in_sizes[0] / D;       // 100000
    const int E = in_sizes[1] / 2;       // 3200000

    float *deg, *isd, *h, *agg;
    cudaGetSymbolAddress((void**)&deg, g_deg);
    cudaGetSymbolAddress((void**)&isd, g_isd);
    cudaGetSymbolAddress((void**)&h, g_h);
    cudaGetSymbolAddress((void**)&agg, g_agg);

    const int gemm_smem = (128 * 128 + 64 * 128) * sizeof(float);   // 96 KB
    const int head_smem = (128 * 40 + 128 * 129) * sizeof(float);   // ~84.5 KB
    cudaFuncSetAttribute(gemm128_kernel<false>,
                         cudaFuncAttributeMaxDynamicSharedMemorySize, gemm_smem);
    cudaFuncSetAttribute(gemm128_kernel<true>,
                         cudaFuncAttributeMaxDynamicSharedMemorySize, gemm_smem);
    cudaFuncSetAttribute(head_kernel,
                         cudaFuncAttributeMaxDynamicSharedMemorySize, head_smem);

    // 0. detect edge_index dtype (int64 vs int32)
    detect_dtype_kernel<<<1, 256>>>(ei);

    // 1. degrees (with self loop) and deg^-1/2
    init_deg_kernel<<<(N + 255) / 256, 256>>>(deg, N);
    count_deg_kernel<<<(E + 255) / 256, 256>>>(ei, deg, E);
    isd_kernel<<<(N + 255) / 256, 256>>>(deg, isd, N);

    const int gemm_grid = (N + 63) / 64;
    const int agg_grid = (E + 7) / 8;       // 1 warp per edge, 8 warps per CTA
    const int head_grid = (N + 127) / 128;

    // 2. layer 1: h = x@W1; agg = h/deg (self loop); agg += scatter
    gemm128_kernel<false><<<gemm_grid, 256, gemm_smem>>>(x, nullptr, W1, h, agg, isd, N);
    agg_kernel<<<agg_grid, 256>>>(ei, h, isd, agg, E);

    // 3. layer 2: h2 = relu(agg + b1)@W2; agg = h2/deg; agg += scatter
    gemm128_kernel<true><<<gemm_grid, 256, gemm_smem>>>(agg, b1, W2, h, agg, isd, N);
    agg_kernel<<<agg_grid, 256>>>(ei, h, isd, agg, E);

    // 4. head: out = relu(agg + b2)@Wl + bl
    head_kernel<<<head_grid, 128, head_smem>>>(agg, b2, Wl, bl, out, N);
}

// round 3
// speedup vs baseline: 2.0871x; 2.0871x over previous
#include <cuda_runtime.h>
#include <cuda_bf16.h>

#define N_NODES_MAX 100000
#define E_MAX 3200000
#define D 128

// Scratch (allocation-free requirement -> __device__ globals)
__device__ __align__(16) float g_isd[N_NODES_MAX];
__device__ __align__(16) float g_h[(size_t)N_NODES_MAX * D];
__device__ __align__(16) float g_agg[(size_t)N_NODES_MAX * D];
__device__ int g_count[N_NODES_MAX];
__device__ int g_scan[N_NODES_MAX];
__device__ int g_rowptr[N_NODES_MAX + 1];
__device__ int g_cursor[N_NODES_MAX];
__device__ int g_bsum[128];
__device__ __align__(16) int2 g_edges[E_MAX];   // (src, norm-as-float-bits) per edge, CSR order
__device__ int g_is64;

// ---------------------------------------------------------------------------
// Edge-index dtype detection (int64 vs int32): node ids < 2^31 so int64 has
// all-zero odd 32-bit words.
// ---------------------------------------------------------------------------
__global__ void detect_dtype_kernel(const unsigned int* __restrict__ w) {
    __shared__ int any_nz;
    if (threadIdx.x == 0) any_nz = 0;
    __syncthreads();
    for (int i = threadIdx.x; i < 1024; i += blockDim.x)
        if (w[2 * i + 1] != 0u) any_nz = 1;
    __syncthreads();
    if (threadIdx.x == 0) g_is64 = any_nz ? 0 : 1;
}

__device__ __forceinline__ int edge_at(const unsigned int* __restrict__ w,
                                       size_t pos, int is64) {
    return (int)(is64 ? w[2 * pos] : w[pos]);
}

// ---------------------------------------------------------------------------
// CSR build: histogram -> scan -> scatter
// ---------------------------------------------------------------------------
__global__ void zero_int_kernel(int* p, int n) {
    int i = blockIdx.x * blockDim.x + threadIdx.x;
    if (i < n) p[i] = 0;
}

__global__ void hist_kernel(const unsigned int* __restrict__ ei, int* count, int E) {
    int e = blockIdx.x * blockDim.x + threadIdx.x;
    if (e < E) {
        int d = edge_at(ei, (size_t)E + e, g_is64);
        atomicAdd(count + d, 1);
    }
}

__global__ void isd_from_count_kernel(const int* __restrict__ count, float* isd, int n) {
    int i = blockIdx.x * blockDim.x + threadIdx.x;
    if (i < n) isd[i] = rsqrtf((float)count[i] + 1.0f);  // +1 self loop
}

// 1024 elements per block (256 threads x 4)
__global__ void scan_partial_kernel(const int* __restrict__ in, int* out,
                                    int* bsum, int n) {
    __shared__ int sm[256];
    int t = threadIdx.x;
    int base = blockIdx.x * 1024 + t * 4;
    int v0 = 0, v1 = 0, v2 = 0, v3 = 0;
    if (base + 0 < n) v0 = in[base + 0];
    if (base + 1 < n) v1 = in[base + 1];
    if (base + 2 < n) v2 = in[base + 2];
    if (base + 3 < n) v3 = in[base + 3];
    int s = v0 + v1 + v2 + v3;
    sm[t] = s;
    __syncthreads();
    for (int off = 1; off < 256; off <<= 1) {
        int x = (t >= off) ? sm[t - off] : 0;
        __syncthreads();
        sm[t] += x;
        __syncthreads();
    }
    int excl = sm[t] - s;
    if (t == 255) bsum[blockIdx.x] = sm[255];
    if (base + 0 < n) out[base + 0] = excl; excl += v0;
    if (base + 1 < n) out[base + 1] = excl; excl += v1;
    if (base + 2 < n) out[base + 2] = excl; excl += v2;
    if (base + 3 < n) out[base + 3] = excl;
}

__global__ void scan_bsum_kernel(int* bsum, int B) {
    __shared__ int sm[128];
    int t = threadIdx.x;
    int v = (t < B) ? bsum[t] : 0;
    sm[t] = v;
    __syncthreads();
    for (int off = 1; off < 128; off <<= 1) {
        int x = (t >= off) ? sm[t - off] : 0;
        __syncthreads();
        sm[t] += x;
        __syncthreads();
    }
    if (t < B) bsum[t] = sm[t] - v;  // exclusive
}

__global__ void scan_add_kernel(const int* __restrict__ scan_local,
                                const int* __restrict__ bsum,
                                int* rowptr, int* cursor, int n, int E) {
    int i = blockIdx.x * blockDim.x + threadIdx.x;
    if (i < n) {
        int v = scan_local[i] + bsum[i >> 10];
        rowptr[i] = v;
        cursor[i] = v;
    }
    if (i == 0) rowptr[n] = E;
}

__global__ void scatter_kernel(const unsigned int* __restrict__ ei,
                               const float* __restrict__ isd,
                               int* cursor, int2* edges, int E) {
    int e = blockIdx.x * blockDim.x + threadIdx.x;
    if (e >= E) return;
    int is64 = g_is64;
    int s = edge_at(ei, (size_t)e, is64);
    int d = edge_at(ei, (size_t)E + e, is64);
    int pos = atomicAdd(cursor + d, 1);
    float norm = isd[s] * isd[d];
    edges[pos] = make_int2(s, __float_as_int(norm));
}

// ---------------------------------------------------------------------------
// GEMM: [M,128] @ [128,128] -> Hout, optional fused relu(x + bias_in) on input.
// Tile: 64 rows x 128 cols per CTA of 256 threads. In-place safe.
// ---------------------------------------------------------------------------
template <bool IN_TRANS>
__global__ void gemm128_kernel(const float* __restrict__ A,
                               const float* __restrict__ bias_in,
                               const float* __restrict__ W,
                               float* __restrict__ Hout,
                               int M) {
    extern __shared__ float sm[];
    float* Ws = sm;             // 128*128
    float* As = sm + 128 * 128; // 64*128

    const int tid = threadIdx.x;
    const int r0 = blockIdx.x * 64;

    const float4* W4 = (const float4*)W;
    float4* Ws4 = (float4*)Ws;
#pragma unroll
    for (int i = 0; i < 16; i++) Ws4[tid + i * 256] = W4[tid + i * 256];

    float4* As4 = (float4*)As;
#pragma unroll
    for (int i = 0; i < 8; i++) {
        int idx = tid + i * 256;
        int row = r0 + (idx >> 5);
        float4 v = make_float4(0.f, 0.f, 0.f, 0.f);
        if (row < M) {
            v = ((const float4*)A)[(size_t)row * 32 + (idx & 31)];
            if (IN_TRANS) {
                float4 b = ((const float4*)bias_in)[idx & 31];
                v.x = fmaxf(v.x + b.x, 0.f);
                v.y = fmaxf(v.y + b.y, 0.f);
                v.z = fmaxf(v.z + b.z, 0.f);
                v.w = fmaxf(v.w + b.w, 0.f);
            }
        }
        As4[idx] = v;
    }
    __syncthreads();

    const int tx = tid & 31;
    const int ty = tid >> 5;
    float acc[8][4] = {};

#pragma unroll 4
    for (int k = 0; k < 128; k++) {
        float4 w = ((const float4*)Ws)[k * 32 + tx];
#pragma unroll
        for (int i = 0; i < 8; i++) {
            float a = As[(ty * 8 + i) * 128 + k];
            acc[i][0] += a * w.x;
            acc[i][1] += a * w.y;
            acc[i][2] += a * w.z;
            acc[i][3] += a * w.w;
        }
    }

#pragma unroll
    for (int i = 0; i < 8; i++) {
        int row = r0 + ty * 8 + i;
        if (row < M)
            ((float4*)Hout)[(size_t)row * 32 + tx] =
                make_float4(acc[i][0], acc[i][1], acc[i][2], acc[i][3]);
    }
}

// ---------------------------------------------------------------------------
// CSR gather aggregation: one warp per destination node; lane owns one float4.
// agg[n] = h[n]/deg(n) + sum_{e in CSR(n)} h[src_e] * norm_e
// ---------------------------------------------------------------------------
__global__ void gather_kernel(const int2* __restrict__ edges,
                              const int* __restrict__ rowptr,
                              const float* __restrict__ h,
                              const float* __restrict__ isd,
                              float* __restrict__ agg, int N) {
    int warp = (blockIdx.x * blockDim.x + threadIdx.x) >> 5;
    int lane = threadIdx.x & 31;
    if (warp >= N) return;

    const float4* h4 = (const float4*)h;
    int start = rowptr[warp];
    int end = rowptr[warp + 1];

    float s = isd[warp];
    float self = s * s;  // 1/deg
    float4 a = h4[(size_t)warp * 32 + lane];
    float4 acc = make_float4(a.x * self, a.y * self, a.z * self, a.w * self);

    int e = start;
    for (; e + 4 <= end; e += 4) {
        int2 e0 = edges[e + 0];
        int2 e1 = edges[e + 1];
        int2 e2 = edges[e + 2];
        int2 e3 = edges[e + 3];
        float4 v0 = h4[(size_t)e0.x * 32 + lane];
        float4 v1 = h4[(size_t)e1.x * 32 + lane];
        float4 v2 = h4[(size_t)e2.x * 32 + lane];
        float4 v3 = h4[(size_t)e3.x * 32 + lane];
        float w0 = __int_as_float(e0.y), w1 = __int_as_float(e1.y);
        float w2 = __int_as_float(e2.y), w3 = __int_as_float(e3.y);
        acc.x += v0.x * w0 + v1.x * w1 + v2.x * w2 + v3.x * w3;
        acc.y += v0.y * w0 + v1.y * w1 + v2.y * w2 + v3.y * w3;
        acc.z += v0.z * w0 + v1.z * w1 + v2.z * w2 + v3.z * w3;
        acc.w += v0.w * w0 + v1.w * w1 + v2.w * w2 + v3.w * w3;
    }
    for (; e < end; e++) {
        int2 ed = edges[e];
        float4 v = h4[(size_t)ed.x * 32 + lane];
        float w = __int_as_float(ed.y);
        acc.x += v.x * w; acc.y += v.y * w; acc.z += v.z * w; acc.w += v.w * w;
    }
    ((float4*)agg)[(size_t)warp * 32 + lane] = acc;
}

// ---------------------------------------------------------------------------
// Head GEMM: out[M,40] = relu(A + b2) @ Wl + bl
// ---------------------------------------------------------------------------
__global__ void head_kernel(const float* __restrict__ A,
                            const float* __restrict__ b2,
                            const float* __restrict__ Wl,
                            const float* __restrict__ bl,
                            float* __restrict__ out,
                            int M) {
    extern __shared__ float sm[];
    float* Ws = sm;             // 128*40
    float* As = sm + 128 * 40;  // 128*129

    const int tid = threadIdx.x;
    const int r0 = blockIdx.x * 128;

    for (int i = tid; i < 128 * 40; i += 128) Ws[i] = Wl[i];

#pragma unroll
    for (int i = 0; i < 32; i++) {
        int idx = tid + i * 128;
        int lr = idx >> 5;
        int c4 = idx & 31;
        int row = r0 + lr;
        float4 v = make_float4(0.f, 0.f, 0.f, 0.f);
        if (row < M) {
            v = ((const float4*)A)[(size_t)row * 32 + c4];
            float4 b = ((const float4*)b2)[c4];
            v.x = fmaxf(v.x + b.x, 0.f);
            v.y = fmaxf(v.y + b.y, 0.f);
            v.z = fmaxf(v.z + b.z, 0.f);
            v.w = fmaxf(v.w + b.w, 0.f);
        }
        float* dst = As + lr * 129 + c4 * 4;
        dst[0] = v.x; dst[1] = v.y; dst[2] = v.z; dst[3] = v.w;
    }
    __syncthreads();

    const int rg = tid >> 2;
    const int cg = tid & 3;
    float acc[4][10] = {};

    for (int k = 0; k < 128; k++) {
        float w[10];
#pragma unroll
        for (int j = 0; j < 10; j++) w[j] = Ws[k * 40 + cg * 10 + j];
#pragma unroll
        for (int i = 0; i < 4; i++) {
            float a = As[(rg * 4 + i) * 129 + k];
#pragma unroll
            for (int j = 0; j < 10; j++) acc[i][j] += a * w[j];
        }
    }

#pragma unroll
    for (int i = 0; i < 4; i++) {
        int row = r0 + rg * 4 + i;
        if (row < M) {
#pragma unroll
            for (int j = 0; j < 10; j++)
                out[(size_t)row * 40 + cg * 10 + j] = acc[i][j] + bl[cg * 10 + j];
        }
    }
}

// ---------------------------------------------------------------------------
extern "C" void kernel_launch(void* const* d_in, const int* in_sizes, int n_in,
                              void* d_out, int out_size) {
    const float* x = (const float*)d_in[0];
    const unsigned int* ei = (const unsigned int*)d_in[1];
    const float* W1 = (const float*)d_in[2];
    const float* b1 = (const float*)d_in[3];
    const float* W2 = (const float*)d_in[4];
    const float* b2 = (const float*)d_in[5];
    const float* Wl = (const float*)d_in[6];
    const float* bl = (const float*)d_in[7];
    float* out = (float*)d_out;

    const int N = in_sizes[0] / D;     // 100000
    const int E = in_sizes[1] / 2;     // 3200000

    float *isd, *h, *agg;
    int *count, *scan, *rowptr, *cursor, *bsum;
    int2* edges;
    cudaGetSymbolAddress((void**)&isd, g_isd);
    cudaGetSymbolAddress((void**)&h, g_h);
    cudaGetSymbolAddress((void**)&agg, g_agg);
    cudaGetSymbolAddress((void**)&count, g_count);
    cudaGetSymbolAddress((void**)&scan, g_scan);
    cudaGetSymbolAddress((void**)&rowptr, g_rowptr);
    cudaGetSymbolAddress((void**)&cursor, g_cursor);
    cudaGetSymbolAddress((void**)&bsum, g_bsum);
    cudaGetSymbolAddress((void**)&edges, g_edges);

    const int gemm_smem = (128 * 128 + 64 * 128) * sizeof(float);
    const int head_smem = (128 * 40 + 128 * 129) * sizeof(float);
    cudaFuncSetAttribute(gemm128_kernel<false>,
                         cudaFuncAttributeMaxDynamicSharedMemorySize, gemm_smem);
    cudaFuncSetAttribute(gemm128_kernel<true>,
                         cudaFuncAttributeMaxDynamicSharedMemorySize, gemm_smem);
    cudaFuncSetAttribute(head_kernel,
                         cudaFuncAttributeMaxDynamicSharedMemorySize, head_smem);

    const int nb = (N + 255) / 256;
    const int eb = (E + 255) / 256;
    const int scan_blocks = (N + 1023) / 1024;   // 98

    // 0. dtype + CSR build
    detect_dtype_kernel<<<1, 256>>>(ei);
    zero_int_kernel<<<nb, 256>>>(count, N);
    hist_kernel<<<eb, 256>>>(ei, count, E);
    isd_from_count_kernel<<<nb, 256>>>(count, isd, N);
    scan_partial_kernel<<<scan_blocks, 256>>>(count, scan, bsum, N);
    scan_bsum_kernel<<<1, 128>>>(bsum, scan_blocks);
    scan_add_kernel<<<nb, 256>>>(scan, bsum, rowptr, cursor, N, E);
    scatter_kernel<<<eb, 256>>>(ei, isd, cursor, edges, E);

    const int gemm_grid = (N + 63) / 64;
    const int gather_grid = (N + 7) / 8;     // 1 warp per node, 8 warps/CTA
    const int head_grid = (N + 127) / 128;

    // 1. layer 1
    gemm128_kernel<false><<<gemm_grid, 256, gemm_smem>>>(x, nullptr, W1, h, N);
    gather_kernel<<<gather_grid, 256>>>(edges, rowptr, h, isd, agg, N);

    // 2. layer 2
    gemm128_kernel<true><<<gemm_grid, 256, gemm_smem>>>(agg, b1, W2, h, N);
    gather_kernel<<<gather_grid, 256>>>(edges, rowptr, h, isd, agg, N);

    // 3. head
    head_kernel<<<head_grid, 128, head_smem>>>(agg, b2, Wl, bl, out, N);
}

// round 4
// speedup vs baseline: 2.3723x; 1.1366x over previous
#include <cuda_runtime.h>
#include <cuda_fp16.h>

#define N_NODES_MAX 100000
#define E_MAX 3200000
#define D 128

// Scratch (allocation-free requirement -> __device__ globals)
__device__ __align__(16) float g_isd[N_NODES_MAX];
__device__ __align__(16) __half g_h16[(size_t)N_NODES_MAX * D];  // gather source, fp16
__device__ __align__(16) float g_agg[(size_t)N_NODES_MAX * D];
__device__ int g_count[N_NODES_MAX];
__device__ int g_scan[N_NODES_MAX];
__device__ int g_rowptr[N_NODES_MAX + 1];
__device__ int g_cursor[N_NODES_MAX];
__device__ int g_bsum[128];
__device__ __align__(16) int2 g_edges[E_MAX];  // (src, norm bits), CSR order
__device__ int g_is64;

// ---------------------------------------------------------------------------
// Edge-index dtype detection (int64 vs int32): node ids < 2^31 so int64 has
// all-zero odd 32-bit words.
// ---------------------------------------------------------------------------
__global__ void detect_dtype_kernel(const unsigned int* __restrict__ w) {
    __shared__ int any_nz;
    if (threadIdx.x == 0) any_nz = 0;
    __syncthreads();
    for (int i = threadIdx.x; i < 1024; i += blockDim.x)
        if (w[2 * i + 1] != 0u) any_nz = 1;
    __syncthreads();
    if (threadIdx.x == 0) g_is64 = any_nz ? 0 : 1;
}

__device__ __forceinline__ int edge_at(const unsigned int* __restrict__ w,
                                       size_t pos, int is64) {
    return (int)(is64 ? w[2 * pos] : w[pos]);
}

// ---------------------------------------------------------------------------
// CSR build: histogram -> scan -> scatter
// ---------------------------------------------------------------------------
__global__ void zero_int_kernel(int* p, int n) {
    int i = blockIdx.x * blockDim.x + threadIdx.x;
    if (i < n) p[i] = 0;
}

__global__ void hist_kernel(const unsigned int* __restrict__ ei, int* count, int E) {
    int e = blockIdx.x * blockDim.x + threadIdx.x;
    if (e < E) {
        int d = edge_at(ei, (size_t)E + e, g_is64);
        atomicAdd(count + d, 1);
    }
}

__global__ void isd_from_count_kernel(const int* __restrict__ count, float* isd, int n) {
    int i = blockIdx.x * blockDim.x + threadIdx.x;
    if (i < n) isd[i] = rsqrtf((float)count[i] + 1.0f);  // +1 self loop
}

// 1024 elements per block (256 threads x 4)
__global__ void scan_partial_kernel(const int* __restrict__ in, int* out,
                                    int* bsum, int n) {
    __shared__ int sm[256];
    int t = threadIdx.x;
    int base = blockIdx.x * 1024 + t * 4;
    int v0 = 0, v1 = 0, v2 = 0, v3 = 0;
    if (base + 0 < n) v0 = in[base + 0];
    if (base + 1 < n) v1 = in[base + 1];
    if (base + 2 < n) v2 = in[base + 2];
    if (base + 3 < n) v3 = in[base + 3];
    int s = v0 + v1 + v2 + v3;
    sm[t] = s;
    __syncthreads();
    for (int off = 1; off < 256; off <<= 1) {
        int x = (t >= off) ? sm[t - off] : 0;
        __syncthreads();
        sm[t] += x;
        __syncthreads();
    }
    int excl = sm[t] - s;
    if (t == 255) bsum[blockIdx.x] = sm[255];
    if (base + 0 < n) out[base + 0] = excl; excl += v0;
    if (base + 1 < n) out[base + 1] = excl; excl += v1;
    if (base + 2 < n) out[base + 2] = excl; excl += v2;
    if (base + 3 < n) out[base + 3] = excl;
}

__global__ void scan_bsum_kernel(int* bsum, int B) {
    __shared__ int sm[128];
    int t = threadIdx.x;
    int v = (t < B) ? bsum[t] : 0;
    sm[t] = v;
    __syncthreads();
    for (int off = 1; off < 128; off <<= 1) {
        int x = (t >= off) ? sm[t - off] : 0;
        __syncthreads();
        sm[t] += x;
        __syncthreads();
    }
    if (t < B) bsum[t] = sm[t] - v;  // exclusive
}

__global__ void scan_add_kernel(const int* __restrict__ scan_local,
                                const int* __restrict__ bsum,
                                int* rowptr, int* cursor, int n, int E) {
    int i = blockIdx.x * blockDim.x + threadIdx.x;
    if (i < n) {
        int v = scan_local[i] + bsum[i >> 10];
        rowptr[i] = v;
        cursor[i] = v;
    }
    if (i == 0) rowptr[n] = E;
}

__global__ void scatter_kernel(const unsigned int* __restrict__ ei,
                               const float* __restrict__ isd,
                               int* cursor, int2* edges, int E) {
    int e = blockIdx.x * blockDim.x + threadIdx.x;
    if (e >= E) return;
    int is64 = g_is64;
    int s = edge_at(ei, (size_t)e, is64);
    int d = edge_at(ei, (size_t)E + e, is64);
    int pos = atomicAdd(cursor + d, 1);
    float norm = isd[s] * isd[d];
    edges[pos] = make_int2(s, __float_as_int(norm));
}

// ---------------------------------------------------------------------------
// GEMM: [M,128] @ [128,128] -> Hout (fp16), optional fused relu(x + bias_in).
// Tile: 64 rows x 128 cols per CTA of 256 threads.
// ---------------------------------------------------------------------------
template <bool IN_TRANS>
__global__ void gemm128_kernel(const float* __restrict__ A,
                               const float* __restrict__ bias_in,
                               const float* __restrict__ W,
                               __half* __restrict__ Hout,
                               int M) {
    extern __shared__ float sm[];
    float* Ws = sm;             // 128*128
    float* As = sm + 128 * 128; // 64*128

    const int tid = threadIdx.x;
    const int r0 = blockIdx.x * 64;

    const float4* W4 = (const float4*)W;
    float4* Ws4 = (float4*)Ws;
#pragma unroll
    for (int i = 0; i < 16; i++) Ws4[tid + i * 256] = W4[tid + i * 256];

    float4* As4 = (float4*)As;
#pragma unroll
    for (int i = 0; i < 8; i++) {
        int idx = tid + i * 256;
        int row = r0 + (idx >> 5);
        float4 v = make_float4(0.f, 0.f, 0.f, 0.f);
        if (row < M) {
            v = ((const float4*)A)[(size_t)row * 32 + (idx & 31)];
            if (IN_TRANS) {
                float4 b = ((const float4*)bias_in)[idx & 31];
                v.x = fmaxf(v.x + b.x, 0.f);
                v.y = fmaxf(v.y + b.y, 0.f);
                v.z = fmaxf(v.z + b.z, 0.f);
                v.w = fmaxf(v.w + b.w, 0.f);
            }
        }
        As4[idx] = v;
    }
    __syncthreads();

    const int tx = tid & 31;   // cols tx*4..tx*4+3
    const int ty = tid >> 5;   // rows ty*8..ty*8+7
    float acc[8][4] = {};

#pragma unroll 4
    for (int k = 0; k < 128; k++) {
        float4 w = ((const float4*)Ws)[k * 32 + tx];
#pragma unroll
        for (int i = 0; i < 8; i++) {
            float a = As[(ty * 8 + i) * 128 + k];
            acc[i][0] += a * w.x;
            acc[i][1] += a * w.y;
            acc[i][2] += a * w.z;
            acc[i][3] += a * w.w;
        }
    }

#pragma unroll
    for (int i = 0; i < 8; i++) {
        int row = r0 + ty * 8 + i;
        if (row < M) {
            __half2 lo = __floats2half2_rn(acc[i][0], acc[i][1]);
            __half2 hi = __floats2half2_rn(acc[i][2], acc[i][3]);
            // 4 halves = one uint2 at half-offset tx*4
            uint2 pack;
            pack.x = *(unsigned int*)&lo;
            pack.y = *(unsigned int*)&hi;
            ((uint2*)Hout)[(size_t)row * 32 + tx] = pack;
        }
    }
}

// ---------------------------------------------------------------------------
// CSR gather aggregation (fp16 source, fp32 accumulate).
// One warp per destination node; lane owns 4 columns (uint2 = 4 halves).
// agg[n] = h16[n]/deg(n) + sum_{e in CSR(n)} h16[src_e] * norm_e
// ---------------------------------------------------------------------------
__device__ __forceinline__ void fma4_h(float4& acc, uint2 p, float w) {
    float2 lo = __half22float2(*(__half2*)&p.x);
    float2 hi = __half22float2(*(__half2*)&p.y);
    acc.x += lo.x * w; acc.y += lo.y * w;
    acc.z += hi.x * w; acc.w += hi.y * w;
}

__global__ void gather_kernel(const int2* __restrict__ edges,
                              const int* __restrict__ rowptr,
                              const __half* __restrict__ h,
                              const float* __restrict__ isd,
                              float* __restrict__ agg, int N) {
    int warp = (blockIdx.x * blockDim.x + threadIdx.x) >> 5;
    int lane = threadIdx.x & 31;
    if (warp >= N) return;

    const uint2* h4 = (const uint2*)h;
    int start = rowptr[warp];
    int end = rowptr[warp + 1];

    float s = isd[warp];
    float self = s * s;  // 1/deg
    float4 acc = make_float4(0.f, 0.f, 0.f, 0.f);
    fma4_h(acc, h4[(size_t)warp * 32 + lane], self);

    int e = start;
    for (; e + 4 <= end; e += 4) {
        int2 e0 = edges[e + 0];
        int2 e1 = edges[e + 1];
        int2 e2 = edges[e + 2];
        int2 e3 = edges[e + 3];
        uint2 v0 = h4[(size_t)e0.x * 32 + lane];
        uint2 v1 = h4[(size_t)e1.x * 32 + lane];
        uint2 v2 = h4[(size_t)e2.x * 32 + lane];
        uint2 v3 = h4[(size_t)e3.x * 32 + lane];
        fma4_h(acc, v0, __int_as_float(e0.y));
        fma4_h(acc, v1, __int_as_float(e1.y));
        fma4_h(acc, v2, __int_as_float(e2.y));
        fma4_h(acc, v3, __int_as_float(e3.y));
    }
    for (; e < end; e++) {
        int2 ed = edges[e];
        fma4_h(acc, h4[(size_t)ed.x * 32 + lane], __int_as_float(ed.y));
    }
    ((float4*)agg)[(size_t)warp * 32 + lane] = acc;
}

// ---------------------------------------------------------------------------
// Head GEMM: out[M,40] = relu(A + b2) @ Wl + bl
// ---------------------------------------------------------------------------
__global__ void head_kernel(const float* __restrict__ A,
                            const float* __restrict__ b2,
                            const float* __restrict__ Wl,
                            const float* __restrict__ bl,
                            float* __restrict__ out,
                            int M) {
    extern __shared__ float sm[];
    float* Ws = sm;             // 128*40
    float* As = sm + 128 * 40;  // 128*129

    const int tid = threadIdx.x;
    const int r0 = blockIdx.x * 128;

    for (int i = tid; i < 128 * 40; i += 128) Ws[i] = Wl[i];

#pragma unroll
    for (int i = 0; i < 32; i++) {
        int idx = tid + i * 128;
        int lr = idx >> 5;
        int c4 = idx & 31;
        int row = r0 + lr;
        float4 v = make_float4(0.f, 0.f, 0.f, 0.f);
        if (row < M) {
            v = ((const float4*)A)[(size_t)row * 32 + c4];
            float4 b = ((const float4*)b2)[c4];
            v.x = fmaxf(v.x + b.x, 0.f);
            v.y = fmaxf(v.y + b.y, 0.f);
            v.z = fmaxf(v.z + b.z, 0.f);
            v.w = fmaxf(v.w + b.w, 0.f);
        }
        float* dst = As + lr * 129 + c4 * 4;
        dst[0] = v.x; dst[1] = v.y; dst[2] = v.z; dst[3] = v.w;
    }
    __syncthreads();

    const int rg = tid >> 2;
    const int cg = tid & 3;
    float acc[4][10] = {};

    for (int k = 0; k < 128; k++) {
        float w[10];
#pragma unroll
        for (int j = 0; j < 10; j++) w[j] = Ws[k * 40 + cg * 10 + j];
#pragma unroll
        for (int i = 0; i < 4; i++) {
            float a = As[(rg * 4 + i) * 129 + k];
#pragma unroll
            for (int j = 0; j < 10; j++) acc[i][j] += a * w[j];
        }
    }

#pragma unroll
    for (int i = 0; i < 4; i++) {
        int row = r0 + rg * 4 + i;
        if (row < M) {
#pragma unroll
            for (int j = 0; j < 10; j++)
                out[(size_t)row * 40 + cg * 10 + j] = acc[i][j] + bl[cg * 10 + j];
        }
    }
}

// ---------------------------------------------------------------------------
extern "C" void kernel_launch(void* const* d_in, const int* in_sizes, int n_in,
                              void* d_out, int out_size) {
    const float* x = (const float*)d_in[0];
    const unsigned int* ei = (const unsigned int*)d_in[1];
    const float* W1 = (const float*)d_in[2];
    const float* b1 = (const float*)d_in[3];
    const float* W2 = (const float*)d_in[4];
    const float* b2 = (const float*)d_in[5];
    const float* Wl = (const float*)d_in[6];
    const float* bl = (const float*)d_in[7];
    float* out = (float*)d_out;

    const int N = in_sizes[0] / D;     // 100000
    const int E = in_sizes[1] / 2;     // 3200000

    float *isd, *agg;
    __half* h16;
    int *count, *scan, *rowptr, *cursor, *bsum;
    int2* edges;
    cudaGetSymbolAddress((void**)&isd, g_isd);
    cudaGetSymbolAddress((void**)&h16, g_h16);
    cudaGetSymbolAddress((void**)&agg, g_agg);
    cudaGetSymbolAddress((void**)&count, g_count);
    cudaGetSymbolAddress((void**)&scan, g_scan);
    cudaGetSymbolAddress((void**)&rowptr, g_rowptr);
    cudaGetSymbolAddress((void**)&cursor, g_cursor);
    cudaGetSymbolAddress((void**)&bsum, g_bsum);
    cudaGetSymbolAddress((void**)&edges, g_edges);

    const int gemm_smem = (128 * 128 + 64 * 128) * sizeof(float);
    const int head_smem = (128 * 40 + 128 * 129) * sizeof(float);
    cudaFuncSetAttribute(gemm128_kernel<false>,
                         cudaFuncAttributeMaxDynamicSharedMemorySize, gemm_smem);
    cudaFuncSetAttribute(gemm128_kernel<true>,
                         cudaFuncAttributeMaxDynamicSharedMemorySize, gemm_smem);
    cudaFuncSetAttribute(head_kernel,
                         cudaFuncAttributeMaxDynamicSharedMemorySize, head_smem);

    const int nb = (N + 255) / 256;
    const int eb = (E + 255) / 256;
    const int scan_blocks = (N + 1023) / 1024;

    // 0. dtype + CSR build
    detect_dtype_kernel<<<1, 256>>>(ei);
    zero_int_kernel<<<nb, 256>>>(count, N);
    hist_kernel<<<eb, 256>>>(ei, count, E);
    isd_from_count_kernel<<<nb, 256>>>(count, isd, N);
    scan_partial_kernel<<<scan_blocks, 256>>>(count, scan, bsum, N);
    scan_bsum_kernel<<<1, 128>>>(bsum, scan_blocks);
    scan_add_kernel<<<nb, 256>>>(scan, bsum, rowptr, cursor, N, E);
    scatter_kernel<<<eb, 256>>>(ei, isd, cursor, edges, E);

    const int gemm_grid = (N + 63) / 64;
    const int gather_grid = (N + 7) / 8;   // 1 warp per node, 8 warps/CTA
    const int head_grid = (N + 127) / 128;

    // 1. layer 1
    gemm128_kernel<false><<<gemm_grid, 256, gemm_smem>>>(x, nullptr, W1, h16, N);
    gather_kernel<<<gather_grid, 256>>>(edges, rowptr, h16, isd, agg, N);

    // 2. layer 2
    gemm128_kernel<true><<<gemm_grid, 256, gemm_smem>>>(agg, b1, W2, h16, N);
    gather_kernel<<<gather_grid, 256>>>(edges, rowptr, h16, isd, agg, N);

    // 3. head
    head_kernel<<<head_grid, 128, head_smem>>>(agg, b2, Wl, bl, out, N);
}

// round 5
// speedup vs baseline: 3.2408x; 1.3661x over previous
#include <cuda_runtime.h>
#include <cuda_fp16.h>

#define N_NODES_MAX 100000
#define E_MAX 3200000
#define D 128

// Scratch (allocation-free requirement -> __device__ globals)
__device__ __align__(16) float g_isd[N_NODES_MAX];
__device__ __align__(16) __half g_h16[(size_t)N_NODES_MAX * D];  // gather source, fp16
__device__ __align__(16) float g_agg[(size_t)N_NODES_MAX * D];
__device__ int g_count[N_NODES_MAX];
__device__ int g_scan[N_NODES_MAX];
__device__ int g_rowptr[N_NODES_MAX + 1];
__device__ int g_cursor[N_NODES_MAX];
__device__ int g_bsum[128];
__device__ __align__(16) int2 g_edges[E_MAX];  // (src, norm bits), CSR order
__device__ int g_is64;
__device__ __align__(16) __half g_W1t[128 * 128];  // W1^T fp16 [n][k]
__device__ __align__(16) __half g_W2t[128 * 128];  // W2^T fp16 [n][k]

// ---------------------------------------------------------------------------
// init: zero count histogram; block 0 also detects edge_index dtype
// (int64 vs int32: node ids < 2^31 so int64 has all-zero odd 32-bit words)
// ---------------------------------------------------------------------------
__global__ void init_kernel(const unsigned int* __restrict__ w, int* count, int n) {
    int i = blockIdx.x * blockDim.x + threadIdx.x;
    if (i < n) count[i] = 0;
    if (blockIdx.x == 0) {
        __shared__ int any_nz;
        if (threadIdx.x == 0) any_nz = 0;
        __syncthreads();
        for (int j = threadIdx.x; j < 1024; j += blockDim.x)
            if (w[2 * j + 1] != 0u) any_nz = 1;
        __syncthreads();
        if (threadIdx.x == 0) g_is64 = any_nz ? 0 : 1;
    }
}

__device__ __forceinline__ int edge_at(const unsigned int* __restrict__ w,
                                       size_t pos, int is64) {
    return (int)(is64 ? w[2 * pos] : w[pos]);
}

__global__ void hist_kernel(const unsigned int* __restrict__ ei, int* count, int E) {
    int e = blockIdx.x * blockDim.x + threadIdx.x;
    if (e < E) {
        int d = edge_at(ei, (size_t)E + e, g_is64);
        atomicAdd(count + d, 1);
    }
}

// ---------------------------------------------------------------------------
// Weight prep: Wt16[n][k] = (half)W[k][n]
// ---------------------------------------------------------------------------
__global__ void wt_prep_kernel(const float* __restrict__ W, __half* __restrict__ Wt) {
    int idx = blockIdx.x * blockDim.x + threadIdx.x;  // 16384
    int n = idx >> 7, k = idx & 127;
    Wt[idx] = __float2half_rn(W[k * 128 + n]);
}

// ---------------------------------------------------------------------------
// Scan chain (1024 elems/block); scan_partial also emits isd = rsqrt(deg+1)
// ---------------------------------------------------------------------------
__global__ void scan_partial_kernel(const int* __restrict__ in, int* out,
                                    int* bsum, float* isd, int n) {
    __shared__ int sm[256];
    int t = threadIdx.x;
    int base = blockIdx.x * 1024 + t * 4;
    int v0 = 0, v1 = 0, v2 = 0, v3 = 0;
    if (base + 0 < n) { v0 = in[base + 0]; isd[base + 0] = rsqrtf((float)v0 + 1.f); }
    if (base + 1 < n) { v1 = in[base + 1]; isd[base + 1] = rsqrtf((float)v1 + 1.f); }
    if (base + 2 < n) { v2 = in[base + 2]; isd[base + 2] = rsqrtf((float)v2 + 1.f); }
    if (base + 3 < n) { v3 = in[base + 3]; isd[base + 3] = rsqrtf((float)v3 + 1.f); }
    int s = v0 + v1 + v2 + v3;
    sm[t] = s;
    __syncthreads();
    for (int off = 1; off < 256; off <<= 1) {
        int x = (t >= off) ? sm[t - off] : 0;
        __syncthreads();
        sm[t] += x;
        __syncthreads();
    }
    int excl = sm[t] - s;
    if (t == 255) bsum[blockIdx.x] = sm[255];
    if (base + 0 < n) out[base + 0] = excl; excl += v0;
    if (base + 1 < n) out[base + 1] = excl; excl += v1;
    if (base + 2 < n) out[base + 2] = excl; excl += v2;
    if (base + 3 < n) out[base + 3] = excl;
}

__global__ void scan_bsum_kernel(int* bsum, int B) {
    __shared__ int sm[128];
    int t = threadIdx.x;
    int v = (t < B) ? bsum[t] : 0;
    sm[t] = v;
    __syncthreads();
    for (int off = 1; off < 128; off <<= 1) {
        int x = (t >= off) ? sm[t - off] : 0;
        __syncthreads();
        sm[t] += x;
        __syncthreads();
    }
    if (t < B) bsum[t] = sm[t] - v;  // exclusive
}

__global__ void scan_add_kernel(const int* __restrict__ scan_local,
                                const int* __restrict__ bsum,
                                int* rowptr, int* cursor, int n, int E) {
    int i = blockIdx.x * blockDim.x + threadIdx.x;
    if (i < n) {
        int v = scan_local[i] + bsum[i >> 10];
        rowptr[i] = v;
        cursor[i] = v;
    }
    if (i == 0) rowptr[n] = E;
}

__global__ void scatter_kernel(const unsigned int* __restrict__ ei,
                               const float* __restrict__ isd,
                               int* cursor, int2* edges, int E) {
    int e = blockIdx.x * blockDim.x + threadIdx.x;
    if (e >= E) return;
    int is64 = g_is64;
    int s = edge_at(ei, (size_t)e, is64);
    int d = edge_at(ei, (size_t)E + e, is64);
    int pos = atomicAdd(cursor + d, 1);
    float norm = isd[s] * isd[d];
    edges[pos] = make_int2(s, __float_as_int(norm));
}

// ---------------------------------------------------------------------------
// Tensor-core GEMM: h16[M,128] = (half)(A[M,128]) @ W[128,128]
// A optionally relu(A + bias) pre-transform; fp16 inputs, fp32 accumulate via
// mma.sync.m16n8k16. CTA = 256 thr (8 warps), tile 64 rows; warp grid 4m x 2n,
// warp tile 16x64. smem rows padded to 136 halves -> conflict-free frag loads.
// ---------------------------------------------------------------------------
__device__ __forceinline__ void mma16816(float c[4], unsigned a0, unsigned a1,
                                         unsigned a2, unsigned a3,
                                         unsigned b0, unsigned b1) {
    asm volatile(
        "mma.sync.aligned.m16n8k16.row.col.f32.f16.f16.f32 "
        "{%0,%1,%2,%3}, {%4,%5,%6,%7}, {%8,%9}, {%0,%1,%2,%3};"
        : "+f"(c[0]), "+f"(c[1]), "+f"(c[2]), "+f"(c[3])
        : "r"(a0), "r"(a1), "r"(a2), "r"(a3), "r"(b0), "r"(b1));
}

#define SPAD 136  // padded row stride in halves

template <bool IN_TRANS>
__global__ void gemm_tc_kernel(const float* __restrict__ A,
                               const float* __restrict__ bias_in,
                               const __half* __restrict__ Wt16,  // [n][k]
                               __half* __restrict__ Hout,
                               int M) {
    extern __shared__ __half smh[];
    __half* As = smh;              // 64 x SPAD
    __half* Bs = smh + 64 * SPAD;  // 128 x SPAD

    const int tid = threadIdx.x;
    const int r0 = blockIdx.x * 64;

    // Fill Bs: straight copy of Wt16 (128x128 fp16) into padded rows
    {
        const uint4* src = (const uint4*)Wt16;
#pragma unroll
        for (int i = 0; i < 8; i++) {
            int idx = tid + i * 256;          // 2048 uint4
            int row = idx >> 4, c8 = idx & 15;
            *(uint4*)(Bs + row * SPAD + c8 * 8) = src[idx];
        }
    }
    // Fill As: fp32 -> fp16 (+ optional relu(x+bias))
#pragma unroll
    for (int i = 0; i < 8; i++) {
        int idx = tid + i * 256;              // 2048 float4
        int row = r0 + (idx >> 5);
        int c4 = idx & 31;
        float4 v = make_float4(0.f, 0.f, 0.f, 0.f);
        if (row < M) {
            v = ((const float4*)A)[(size_t)row * 32 + c4];
            if (IN_TRANS) {
                float4 b = ((const float4*)bias_in)[c4];
                v.x = fmaxf(v.x + b.x, 0.f);
                v.y = fmaxf(v.y + b.y, 0.f);
                v.z = fmaxf(v.z + b.z, 0.f);
                v.w = fmaxf(v.w + b.w, 0.f);
            }
        }
        __half2 lo = __floats2half2_rn(v.x, v.y);
        __half2 hi = __floats2half2_rn(v.z, v.w);
        uint2 pack;
        pack.x = *(unsigned*)&lo;
        pack.y = *(unsigned*)&hi;
        *(uint2*)(As + (idx >> 5) * SPAD + c4 * 4) = pack;
    }
    __syncthreads();

    const int warp = tid >> 5;
    const int lane = tid & 31;
    const int g = lane >> 2;      // group row 0..7
    const int tig = lane & 3;     // 0..3
    const int m0 = (warp & 3) * 16;
    const int n0 = (warp >> 2) * 64;

    float c[8][4] = {};
    const __half* Aw = As + (m0 + g) * SPAD + tig * 2;
    const __half* Bw = Bs + (n0 + g) * SPAD + tig * 2;

#pragma unroll
    for (int ks = 0; ks < 8; ks++) {
        int k0 = ks * 16;
        unsigned a0 = *(const unsigned*)(Aw + k0);
        unsigned a1 = *(const unsigned*)(Aw + k0 + 8 * SPAD);
        unsigned a2 = *(const unsigned*)(Aw + k0 + 8);
        unsigned a3 = *(const unsigned*)(Aw + k0 + 8 * SPAD + 8);
#pragma unroll
        for (int t = 0; t < 8; t++) {
            unsigned b0 = *(const unsigned*)(Bw + t * 8 * SPAD + k0);
            unsigned b1 = *(const unsigned*)(Bw + t * 8 * SPAD + k0 + 8);
            mma16816(c[t], a0, a1, a2, a3, b0, b1);
        }
    }

    // Epilogue: fp32 acc -> fp16, direct STG (4 threads cover 16B per row chunk)
#pragma unroll
    for (int t = 0; t < 8; t++) {
        int col = n0 + t * 8 + tig * 2;
        int row0 = r0 + m0 + g;
        int row1 = row0 + 8;
        if (row0 < M) {
            __half2 p = __floats2half2_rn(c[t][0], c[t][1]);
            *(unsigned*)(Hout + (size_t)row0 * 128 + col) = *(unsigned*)&p;
        }
        if (row1 < M) {
            __half2 p = __floats2half2_rn(c[t][2], c[t][3]);
            *(unsigned*)(Hout + (size_t)row1 * 128 + col) = *(unsigned*)&p;
        }
    }
}

// ---------------------------------------------------------------------------
// CSR gather aggregation (fp16 source, fp32 accumulate).
// One warp per destination node; lane owns 4 columns (uint2 = 4 halves).
// ---------------------------------------------------------------------------
__device__ __forceinline__ void fma4_h(float4& acc, uint2 p, float w) {
    float2 lo = __half22float2(*(__half2*)&p.x);
    float2 hi = __half22float2(*(__half2*)&p.y);
    acc.x += lo.x * w; acc.y += lo.y * w;
    acc.z += hi.x * w; acc.w += hi.y * w;
}

__global__ void gather_kernel(const int2* __restrict__ edges,
                              const int* __restrict__ rowptr,
                              const __half* __restrict__ h,
                              const float* __restrict__ isd,
                              float* __restrict__ agg, int N) {
    int warp = (blockIdx.x * blockDim.x + threadIdx.x) >> 5;
    int lane = threadIdx.x & 31;
    if (warp >= N) return;

    const uint2* h4 = (const uint2*)h;
    int start = rowptr[warp];
    int end = rowptr[warp + 1];

    float s = isd[warp];
    float self = s * s;  // 1/deg
    float4 acc = make_float4(0.f, 0.f, 0.f, 0.f);
    fma4_h(acc, h4[(size_t)warp * 32 + lane], self);

    int e = start;
    for (; e + 4 <= end; e += 4) {
        int2 e0 = edges[e + 0];
        int2 e1 = edges[e + 1];
        int2 e2 = edges[e + 2];
        int2 e3 = edges[e + 3];
        uint2 v0 = h4[(size_t)e0.x * 32 + lane];
        uint2 v1 = h4[(size_t)e1.x * 32 + lane];
        uint2 v2 = h4[(size_t)e2.x * 32 + lane];
        uint2 v3 = h4[(size_t)e3.x * 32 + lane];
        fma4_h(acc, v0, __int_as_float(e0.y));
        fma4_h(acc, v1, __int_as_float(e1.y));
        fma4_h(acc, v2, __int_as_float(e2.y));
        fma4_h(acc, v3, __int_as_float(e3.y));
    }
    for (; e < end; e++) {
        int2 ed = edges[e];
        fma4_h(acc, h4[(size_t)ed.x * 32 + lane], __int_as_float(ed.y));
    }
    ((float4*)agg)[(size_t)warp * 32 + lane] = acc;
}

// ---------------------------------------------------------------------------
// Head GEMM: out[M,40] = relu(A + b2) @ Wl + bl   (fp32 SIMT)
// ---------------------------------------------------------------------------
__global__ void head_kernel(const float* __restrict__ A,
                            const float* __restrict__ b2,
                            const float* __restrict__ Wl,
                            const float* __restrict__ bl,
                            float* __restrict__ out,
                            int M) {
    extern __shared__ float sm[];
    float* Ws = sm;             // 128*40
    float* As = sm + 128 * 40;  // 128*129

    const int tid = threadIdx.x;
    const int r0 = blockIdx.x * 128;

    for (int i = tid; i < 128 * 40; i += 128) Ws[i] = Wl[i];

#pragma unroll
    for (int i = 0; i < 32; i++) {
        int idx = tid + i * 128;
        int lr = idx >> 5;
        int c4 = idx & 31;
        int row = r0 + lr;
        float4 v = make_float4(0.f, 0.f, 0.f, 0.f);
        if (row < M) {
            v = ((const float4*)A)[(size_t)row * 32 + c4];
            float4 b = ((const float4*)b2)[c4];
            v.x = fmaxf(v.x + b.x, 0.f);
            v.y = fmaxf(v.y + b.y, 0.f);
            v.z = fmaxf(v.z + b.z, 0.f);
            v.w = fmaxf(v.w + b.w, 0.f);
        }
        float* dst = As + lr * 129 + c4 * 4;
        dst[0] = v.x; dst[1] = v.y; dst[2] = v.z; dst[3] = v.w;
    }
    __syncthreads();

    const int rg = tid >> 2;
    const int cg = tid & 3;
    float acc[4][10] = {};

    for (int k = 0; k < 128; k++) {
        float w[10];
#pragma unroll
        for (int j = 0; j < 10; j++) w[j] = Ws[k * 40 + cg * 10 + j];
#pragma unroll
        for (int i = 0; i < 4; i++) {
            float a = As[(rg * 4 + i) * 129 + k];
#pragma unroll
            for (int j = 0; j < 10; j++) acc[i][j] += a * w[j];
        }
    }

#pragma unroll
    for (int i = 0; i < 4; i++) {
        int row = r0 + rg * 4 + i;
        if (row < M) {
#pragma unroll
            for (int j = 0; j < 10; j++)
                out[(size_t)row * 40 + cg * 10 + j] = acc[i][j] + bl[cg * 10 + j];
        }
    }
}

// ---------------------------------------------------------------------------
extern "C" void kernel_launch(void* const* d_in, const int* in_sizes, int n_in,
                              void* d_out, int out_size) {
    const float* x = (const float*)d_in[0];
    const unsigned int* ei = (const unsigned int*)d_in[1];
    const float* W1 = (const float*)d_in[2];
    const float* b1 = (const float*)d_in[3];
    const float* W2 = (const float*)d_in[4];
    const float* b2 = (const float*)d_in[5];
    const float* Wl = (const float*)d_in[6];
    const float* bl = (const float*)d_in[7];
    float* out = (float*)d_out;

    const int N = in_sizes[0] / D;     // 100000
    const int E = in_sizes[1] / 2;     // 3200000

    float *isd, *agg;
    __half *h16, *W1t, *W2t;
    int *count, *scan, *rowptr, *cursor, *bsum;
    int2* edges;
    cudaGetSymbolAddress((void**)&isd, g_isd);
    cudaGetSymbolAddress((void**)&h16, g_h16);
    cudaGetSymbolAddress((void**)&agg, g_agg);
    cudaGetSymbolAddress((void**)&count, g_count);
    cudaGetSymbolAddress((void**)&scan, g_scan);
    cudaGetSymbolAddress((void**)&rowptr, g_rowptr);
    cudaGetSymbolAddress((void**)&cursor, g_cursor);
    cudaGetSymbolAddress((void**)&bsum, g_bsum);
    cudaGetSymbolAddress((void**)&edges, g_edges);
    cudaGetSymbolAddress((void**)&W1t, g_W1t);
    cudaGetSymbolAddress((void**)&W2t, g_W2t);

    const int gemm_smem = (64 * SPAD + 128 * SPAD) * sizeof(__half);  // ~52 KB
    const int head_smem = (128 * 40 + 128 * 129) * sizeof(float);
    cudaFuncSetAttribute(gemm_tc_kernel<false>,
                         cudaFuncAttributeMaxDynamicSharedMemorySize, gemm_smem);
    cudaFuncSetAttribute(gemm_tc_kernel<true>,
                         cudaFuncAttributeMaxDynamicSharedMemorySize, gemm_smem);
    cudaFuncSetAttribute(head_kernel,
                         cudaFuncAttributeMaxDynamicSharedMemorySize, head_smem);

    const int nb = (N + 255) / 256;
    const int eb = (E + 255) / 256;
    const int scan_blocks = (N + 1023) / 1024;

    // 0. init + dtype, weight prep (independent), histogram, CSR
    init_kernel<<<nb, 256>>>(ei, count, N);
    wt_prep_kernel<<<64, 256>>>(W1, W1t);
    wt_prep_kernel<<<64, 256>>>(W2, W2t);
    hist_kernel<<<eb, 256>>>(ei, count, E);
    scan_partial_kernel<<<scan_blocks, 256>>>(count, scan, bsum, isd, N);
    scan_bsum_kernel<<<1, 128>>>(bsum, scan_blocks);
    scan_add_kernel<<<nb, 256>>>(scan, bsum, rowptr, cursor, N, E);
    scatter_kernel<<<eb, 256>>>(ei, isd, cursor, edges, E);

    const int gemm_grid = (N + 63) / 64;
    const int gather_grid = (N + 7) / 8;
    const int head_grid = (N + 127) / 128;

    // 1. layer 1
    gemm_tc_kernel<false><<<gemm_grid, 256, gemm_smem>>>(x, nullptr, W1t, h16, N);
    gather_kernel<<<gather_grid, 256>>>(edges, rowptr, h16, isd, agg, N);

    // 2. layer 2
    gemm_tc_kernel<true><<<gemm_grid, 256, gemm_smem>>>(agg, b1, W2t, h16, N);
    gather_kernel<<<gather_grid, 256>>>(edges, rowptr, h16, isd, agg, N);

    // 3. head
    head_kernel<<<head_grid, 128, head_smem>>>(agg, b2, Wl, bl, out, N);
}